// round 15
// baseline (speedup 1.0000x reference)
#include <cuda_runtime.h>
#include <cuda_bf16.h>
#include <cstdint>

#define EPSF 1.1920928955078125e-07f

// Problem constants
#define B_   32
#define P_   8192
#define SI_  64
#define SO_  32
#define L_   256
#define C_   4096          // 2 * SI * SO
#define YSZ  33554432      // B*P*128

// Device scratch (no allocations allowed)
__device__ float g_logits[B_ * C_];
__device__ float g_V[B_ * C_];
__device__ float g_h[B_ * L_];                // atomically-accumulated hidden pre-act
__device__ __nv_bfloat16 g_mh[B_ * C_];       // mask hi (bf16)
__device__ __nv_bfloat16 g_ml[B_ * C_];       // mask lo residual (bf16)

// ---------------------------------------------------------------------------
// Kernel 1: logits[b,c] = sum_l latent[b,l] * K[side(c)][l, i, o].
// Blocks 0..31 additionally zero g_h (consumed by fused kernel's atomics).
// ---------------------------------------------------------------------------
__global__ void __launch_bounds__(256) k_logits(const float* __restrict__ lat,
                                                const float* __restrict__ Kl,
                                                const float* __restrict__ Kr) {
    __shared__ float slat[B_ * L_];  // 32 KB
    if (blockIdx.x < 32) g_h[blockIdx.x * L_ + threadIdx.x] = 0.f;
    for (int k = threadIdx.x; k < B_ * L_; k += 256) slat[k] = lat[k];
    __syncthreads();

    int c  = blockIdx.x * 32 + (threadIdx.x & 31);
    int bg = threadIdx.x >> 5;                // 0..7 -> batches bg*4..bg*4+3
    const float* Ksrc = (c & 2048) ? Kr : Kl;
    int cc = c & 2047;

    float acc[4] = {0.f, 0.f, 0.f, 0.f};
    const float* s0 = slat + (bg * 4) * L_;
#pragma unroll 4
    for (int l = 0; l < L_; l += 8) {
        float kv[8];
#pragma unroll
        for (int u = 0; u < 8; u++) kv[u] = Ksrc[(size_t)(l + u) * 2048 + cc];
#pragma unroll
        for (int u = 0; u < 8; u++) {
#pragma unroll
            for (int q = 0; q < 4; q++)
                acc[q] += s0[q * L_ + l + u] * kv[u];
        }
    }
#pragma unroll
    for (int q = 0; q < 4; q++)
        g_logits[(size_t)(bg * 4 + q) * C_ + c] = acc[q];
}

// ---------------------------------------------------------------------------
// Kernel 2: warp-per-(b,side,o) column softmax + gumbel-softmax, shfl-only.
// ---------------------------------------------------------------------------
__device__ __forceinline__ float warp_max(float v) {
#pragma unroll
    for (int m = 16; m > 0; m >>= 1) v = fmaxf(v, __shfl_xor_sync(0xffffffffu, v, m));
    return v;
}
__device__ __forceinline__ float warp_sum(float v) {
#pragma unroll
    for (int m = 16; m > 0; m >>= 1) v += __shfl_xor_sync(0xffffffffu, v, m);
    return v;
}

__global__ void __launch_bounds__(256) k_sg(const float* __restrict__ gu,
                                            const float* __restrict__ temp) {
    int w    = (blockIdx.x * blockDim.x + threadIdx.x) >> 5;  // 0..2047
    int lane = threadIdx.x & 31;
    int b    = w >> 6;
    int rem  = w & 63;                 // side*32 + o
    int side = rem >> 5, o = rem & 31;
    int base = b * C_ + side * 2048 + o;

    float a0 = g_logits[base + lane * 32];
    float a1 = g_logits[base + (lane + 32) * 32];
    float mx = warp_max(fmaxf(a0, a1));
    float e0 = __expf(a0 - mx), e1 = __expf(a1 - mx);
    float inv = 1.0f / warp_sum(e0 + e1);
    float p0 = e0 * inv, p1 = e1 * inv;
    g_V[base + lane * 32]        = p0;
    g_V[base + (lane + 32) * 32] = p1;

    float tc = fmaxf(fminf(fmaxf(temp[0], EPSF), 2.0f), EPSF);
    float invt = 1.0f / tc;

    float u0 = fmaxf(gu[base + lane * 32], EPSF);
    float u1 = fmaxf(gu[base + (lane + 32) * 32], EPSF);
    float g0 = -__logf(-__logf(u0) + EPSF);
    float g1 = -__logf(-__logf(u1) + EPSF);
    float l0 = (__logf(p0 + EPSF) + g0) * invt;
    float l1 = (__logf(p1 + EPSF) + g1) * invt;
    mx = warp_max(fmaxf(l0, l1));
    e0 = __expf(l0 - mx); e1 = __expf(l1 - mx);
    inv = 1.0f / warp_sum(e0 + e1);
    float m0 = e0 * inv, m1 = e1 * inv;

    __nv_bfloat16 h0 = __float2bfloat16_rn(m0);
    __nv_bfloat16 h1 = __float2bfloat16_rn(m1);
    __nv_bfloat16 q0 = __float2bfloat16_rn(m0 - __bfloat162float(h0));
    __nv_bfloat16 q1 = __float2bfloat16_rn(m1 - __bfloat162float(h1));
    size_t i0 = (size_t)b * C_ + lane * 64 + side * 32 + o;
    size_t i1 = (size_t)b * C_ + (lane + 32) * 64 + side * 32 + o;
    g_mh[i0] = h0; g_ml[i0] = q0;
    g_mh[i1] = h1; g_ml[i1] = q1;
}

// ---------------------------------------------------------------------------
// Kernel 3 (FUSED): blockIdx.x < 32  -> main tensor-core GEMM tile (256 rows,
//                   each warp computes TWO 16-row m-tiles reusing B frags)
//                   blockIdx.x >= 32 -> one of 512 h-partial blocks.
// ---------------------------------------------------------------------------
#define LDSM4(r, a) \
    asm volatile("ldmatrix.sync.aligned.m8n8.x4.shared.b16 {%0,%1,%2,%3}, [%4];" \
        : "=r"((r)[0]), "=r"((r)[1]), "=r"((r)[2]), "=r"((r)[3]) : "r"(a))
#define LDSM4T(r, a) \
    asm volatile("ldmatrix.sync.aligned.m8n8.x4.trans.shared.b16 {%0,%1,%2,%3}, [%4];" \
        : "=r"((r)[0]), "=r"((r)[1]), "=r"((r)[2]), "=r"((r)[3]) : "r"(a))
#define MMA16816(d, a, b0, b1) \
    asm volatile("mma.sync.aligned.m16n8k16.row.col.f32.bf16.bf16.f32 " \
        "{%0,%1,%2,%3}, {%4,%5,%6,%7}, {%8,%9}, {%0,%1,%2,%3};" \
        : "+f"((d)[0]), "+f"((d)[1]), "+f"((d)[2]), "+f"((d)[3]) \
        : "r"((a)[0]), "r"((a)[1]), "r"((a)[2]), "r"((a)[3]), "r"(b0), "r"(b1))

#define SM_MH 0
#define SM_ML 9216
#define SM_XH 18432
#define SM_XL 55296            // 18432 + 256*144
#define SM_TOT 92160           // 55296 + 256*144

extern __shared__ char smc[];

__device__ __forceinline__ void h_part_body(const float* __restrict__ W1, int hb) {
    float* Vs = (float*)smc;                 // B_*68 floats = 8704 B
    int jt = hb & 7;
    int ks = hb >> 3;                        // 0..63, 64 k each

    for (int idx = threadIdx.x; idx < B_ * 64; idx += 256) {
        int b = idx >> 6, k = idx & 63;
        Vs[b * 68 + k] = g_V[b * C_ + ks * 64 + k];
    }
    __syncthreads();

    int j  = jt * 32 + (threadIdx.x & 31);
    int bg = threadIdx.x >> 5;

    float acc[4] = {0.f, 0.f, 0.f, 0.f};
    const float* wp = W1 + (size_t)(ks * 64) * 256 + j;
#pragma unroll
    for (int kb = 0; kb < 8; kb++) {
        float wv[8];
#pragma unroll
        for (int u = 0; u < 8; u++) wv[u] = wp[(size_t)(kb * 8 + u) * 256];
#pragma unroll
        for (int u = 0; u < 8; u++) {
            int k = kb * 8 + u;
#pragma unroll
            for (int q = 0; q < 4; q++)
                acc[q] += Vs[(bg * 4 + q) * 68 + k] * wv[u];
        }
    }
#pragma unroll
    for (int q = 0; q < 4; q++)
        atomicAdd(&g_h[(size_t)(bg * 4 + q) * L_ + j], acc[q]);
}

__global__ void __launch_bounds__(256) k_fused(const float* __restrict__ x,
                                               float* __restrict__ y,
                                               const float* __restrict__ W1) {
    if (blockIdx.x >= 32) {                  // ---- h-partial branch ----
        h_part_body(W1, (blockIdx.x - 32) * 32 + blockIdx.y);
        return;
    }

    // ---- main GEMM branch: 256 rows/block, 2 m-tiles per warp ----
    int tid = threadIdx.x, lane = tid & 31, w = tid >> 5;
    int b = blockIdx.y;
    int pbase = blockIdx.x * 256;

    uint32_t sb = (uint32_t)__cvta_generic_to_shared(smc);

    const uint4* mh4 = (const uint4*)(g_mh + (size_t)b * C_);
    const uint4* ml4 = (const uint4*)(g_ml + (size_t)b * C_);
#pragma unroll
    for (int k = 0; k < 2; k++) {
        int idx = tid + k * 256;
        int row = idx >> 3, ch = idx & 7;
        *(uint4*)(smc + SM_MH + row * 144 + ch * 16) = mh4[idx];
        *(uint4*)(smc + SM_ML + row * 144 + ch * 16) = ml4[idx];
    }

    const float4* xg = (const float4*)(x + ((size_t)b * P_ + pbase) * SI_);
#pragma unroll
    for (int k = 0; k < 16; k++) {
        int idx = tid + k * 256;             // 0..4095 = 256 rows x 16 float4
        int row = idx >> 4, f4 = idx & 15;
        float4 v = __ldcs(&xg[idx]);         // streaming read-once
        __nv_bfloat16 h0 = __float2bfloat16_rn(v.x);
        __nv_bfloat16 h1 = __float2bfloat16_rn(v.y);
        __nv_bfloat16 h2 = __float2bfloat16_rn(v.z);
        __nv_bfloat16 h3 = __float2bfloat16_rn(v.w);
        __nv_bfloat16 l0 = __float2bfloat16_rn(v.x - __bfloat162float(h0));
        __nv_bfloat16 l1 = __float2bfloat16_rn(v.y - __bfloat162float(h1));
        __nv_bfloat16 l2 = __float2bfloat16_rn(v.z - __bfloat162float(h2));
        __nv_bfloat16 l3 = __float2bfloat16_rn(v.w - __bfloat162float(h3));
        __nv_bfloat162 hA = {h0, h1}, hB = {h2, h3};
        __nv_bfloat162 lA = {l0, l1}, lB = {l2, l3};
        uint2 hp = make_uint2(*(uint32_t*)&hA, *(uint32_t*)&hB);
        uint2 lp = make_uint2(*(uint32_t*)&lA, *(uint32_t*)&lB);
        *(uint2*)(smc + SM_XH + row * 144 + f4 * 8) = hp;
        *(uint2*)(smc + SM_XL + row * 144 + f4 * 8) = lp;
    }
    __syncthreads();

    float d[2][8][4];
#pragma unroll
    for (int mt = 0; mt < 2; mt++)
#pragma unroll
        for (int nt = 0; nt < 8; nt++)
#pragma unroll
            for (int q = 0; q < 4; q++) d[mt][nt][q] = 0.f;

    int lrow = lane & 15;
    uint32_t lcol = (lane >> 4) * 16;

#pragma unroll
    for (int ks = 0; ks < 4; ks++) {
        // B fragments loaded ONCE per ks, reused across both m-tiles
        uint32_t bh[4][4], bl[4][4];
        uint32_t brow = (uint32_t)((ks * 16 + lrow) * 144) + lcol;
#pragma unroll
        for (int np = 0; np < 4; np++) {
            LDSM4T(bh[np], sb + SM_MH + brow + np * 32);
            LDSM4T(bl[np], sb + SM_ML + brow + np * 32);
        }
#pragma unroll
        for (int mt = 0; mt < 2; mt++) {
            uint32_t ah[4], al[4];
            uint32_t aoff = (uint32_t)((w * 32 + mt * 16 + lrow) * 144 + ks * 32) + lcol;
            LDSM4(ah, sb + SM_XH + aoff);
            LDSM4(al, sb + SM_XL + aoff);
#pragma unroll
            for (int nt = 0; nt < 8; nt++) {
                uint32_t bh0 = bh[nt >> 1][(nt & 1) * 2], bh1 = bh[nt >> 1][(nt & 1) * 2 + 1];
                uint32_t bl0 = bl[nt >> 1][(nt & 1) * 2], bl1 = bl[nt >> 1][(nt & 1) * 2 + 1];
                MMA16816(d[mt][nt], ah, bh0, bh1);
                MMA16816(d[mt][nt], al, bh0, bh1);
                MMA16816(d[mt][nt], ah, bl0, bl1);
            }
        }
    }

    // epilogue: fragments -> smem [256][72], then coalesced streaming STG.128
    __syncthreads();
    float* eb = (float*)(smc + SM_XH);
    int cb = (lane & 3) * 2;
#pragma unroll
    for (int mt = 0; mt < 2; mt++) {
        int r0 = w * 32 + mt * 16 + (lane >> 2);
#pragma unroll
        for (int nt = 0; nt < 8; nt++) {
            int col = nt * 8 + cb;
            *(float2*)(eb + (size_t)r0 * 72 + col)       = make_float2(d[mt][nt][0], d[mt][nt][1]);
            *(float2*)(eb + (size_t)(r0 + 8) * 72 + col) = make_float2(d[mt][nt][2], d[mt][nt][3]);
        }
    }
    __syncwarp();

    float* yb = y + ((size_t)b * P_ + pbase) * 128;
    int ch = lane & 7;
#define CLIP01(v) fminf(fmaxf((v), 0.f), 1.f)
#pragma unroll
    for (int rg = 0; rg < 8; rg++) {
        int row = w * 32 + rg * 4 + (lane >> 3);
        float4 vl = *(float4*)(eb + (size_t)row * 72 + ch * 4);
        float4 vr = *(float4*)(eb + (size_t)row * 72 + 32 + ch * 4);
        float s0 = vl.x + vr.x, s1 = vl.y + vr.y, s2 = vl.z + vr.z, s3 = vl.w + vr.w;
        float e0 = vl.x - vr.x, e1 = vl.y - vr.y, e2 = vl.z - vr.z, e3 = vl.w - vr.w;
        float* orow = yb + (size_t)row * 128 + ch * 4;
        float4 o;
        o.x = CLIP01(s0); o.y = CLIP01(s1); o.z = CLIP01(s2); o.w = CLIP01(s3);
        __stcs((float4*)(orow), o);
        o.x = CLIP01(s0 - 1.f); o.y = CLIP01(s1 - 1.f); o.z = CLIP01(s2 - 1.f); o.w = CLIP01(s3 - 1.f);
        __stcs((float4*)(orow + 32), o);
        o.x = CLIP01(e0); o.y = CLIP01(e1); o.z = CLIP01(e2); o.w = CLIP01(e3);
        __stcs((float4*)(orow + 64), o);
        o.x = CLIP01(-e0); o.y = CLIP01(-e1); o.z = CLIP01(-e2); o.w = CLIP01(-e3);
        __stcs((float4*)(orow + 96), o);
    }
#undef CLIP01
}

// ---------------------------------------------------------------------------
// Kernel 4: v_encode = leaky(g_h + b1) @ W2 + b2. grid (8 jt, 32 b).
// ---------------------------------------------------------------------------
__global__ void __launch_bounds__(256) k_venc(const float* __restrict__ b1,
                                              const float* __restrict__ W2,
                                              const float* __restrict__ b2,
                                              float* __restrict__ out) {
    int jt = blockIdx.x, b = blockIdx.y;
    int tid = threadIdx.x, lane = tid & 31, w = tid >> 5;
    __shared__ float sh[L_];
    __shared__ float red[8][32];

    float s = g_h[b * L_ + tid] + b1[tid];
    sh[tid] = (s >= 0.f) ? s : 0.01f * s;
    __syncthreads();

    int j = jt * 32 + lane;
    float a = 0.f;
    const float* wp = W2 + (size_t)(w * 32) * L_ + j;
#pragma unroll
    for (int k = 0; k < 32; k++)
        a += sh[w * 32 + k] * wp[(size_t)k * L_];
    red[w][lane] = a;
    __syncthreads();
    if (w == 0) {
        float t = a + b2[j];
#pragma unroll
        for (int q = 1; q < 8; q++) t += red[q][lane];
        out[YSZ + b * L_ + j] = t;
    }
}

// ---------------------------------------------------------------------------
extern "C" void kernel_launch(void* const* d_in, const int* in_sizes, int n_in,
                              void* d_out, int out_size) {
    const float* x    = (const float*)d_in[0];
    const float* lat  = (const float*)d_in[1];
    const float* gu   = (const float*)d_in[2];
    const float* Kl   = (const float*)d_in[3];
    const float* Kr   = (const float*)d_in[4];
    const float* temp = (const float*)d_in[5];
    const float* W1   = (const float*)d_in[6];
    const float* b1   = (const float*)d_in[7];
    const float* W2   = (const float*)d_in[8];
    const float* b2   = (const float*)d_in[9];
    float* out = (float*)d_out;

    cudaFuncSetAttribute(k_fused, cudaFuncAttributeMaxDynamicSharedMemorySize, SM_TOT);

    // 4 serial launches; h_part co-scheduled inside k_fused (x >= 32 blocks).
    k_logits<<<128, 256>>>(lat, Kl, Kr);                 // also zeros g_h
    k_sg<<<256, 256>>>(gu, temp);
    k_fused<<<dim3(48, 32), 256, SM_TOT>>>(x, out, W1);  // 32 main + 16 h_part per y
    k_venc<<<dim3(8, 32), 256>>>(b1, W2, b2, out);
}

// round 16
// speedup vs baseline: 1.1020x; 1.1020x over previous
#include <cuda_runtime.h>
#include <cuda_bf16.h>
#include <cstdint>

#define EPSF 1.1920928955078125e-07f

// Problem constants
#define B_   32
#define P_   8192
#define SI_  64
#define SO_  32
#define L_   256
#define C_   4096          // 2 * SI * SO
#define YSZ  33554432      // B*P*128

// Device scratch (no allocations allowed)
__device__ float g_logits[B_ * C_];
__device__ float g_V[B_ * C_];
__device__ float g_h[B_ * L_];                // atomically-accumulated hidden pre-act
__device__ __nv_bfloat16 g_mh[B_ * C_];       // mask hi (bf16)
__device__ __nv_bfloat16 g_ml[B_ * C_];       // mask lo residual (bf16)

// ---------------------------------------------------------------------------
// Kernel 1: logits[b,c] = sum_l latent[b,l] * K[side(c)][l, i, o].
// Blocks 0..31 additionally zero g_h (consumed by fused kernel's atomics).
// ---------------------------------------------------------------------------
__global__ void __launch_bounds__(256) k_logits(const float* __restrict__ lat,
                                                const float* __restrict__ Kl,
                                                const float* __restrict__ Kr) {
    __shared__ float slat[B_ * L_];  // 32 KB
    if (blockIdx.x < 32) g_h[blockIdx.x * L_ + threadIdx.x] = 0.f;
    for (int k = threadIdx.x; k < B_ * L_; k += 256) slat[k] = lat[k];
    __syncthreads();

    int c  = blockIdx.x * 32 + (threadIdx.x & 31);
    int bg = threadIdx.x >> 5;                // 0..7 -> batches bg*4..bg*4+3
    const float* Ksrc = (c & 2048) ? Kr : Kl;
    int cc = c & 2047;

    float acc[4] = {0.f, 0.f, 0.f, 0.f};
    const float* s0 = slat + (bg * 4) * L_;
#pragma unroll 4
    for (int l = 0; l < L_; l += 8) {
        float kv[8];
#pragma unroll
        for (int u = 0; u < 8; u++) kv[u] = __ldcs(&Ksrc[(size_t)(l + u) * 2048 + cc]);
#pragma unroll
        for (int u = 0; u < 8; u++) {
#pragma unroll
            for (int q = 0; q < 4; q++)
                acc[q] += s0[q * L_ + l + u] * kv[u];
        }
    }
#pragma unroll
    for (int q = 0; q < 4; q++)
        g_logits[(size_t)(bg * 4 + q) * C_ + c] = acc[q];
}

// ---------------------------------------------------------------------------
// Kernel 2: warp-per-(b,side,o) column softmax + gumbel-softmax, shfl-only.
// ---------------------------------------------------------------------------
__device__ __forceinline__ float warp_max(float v) {
#pragma unroll
    for (int m = 16; m > 0; m >>= 1) v = fmaxf(v, __shfl_xor_sync(0xffffffffu, v, m));
    return v;
}
__device__ __forceinline__ float warp_sum(float v) {
#pragma unroll
    for (int m = 16; m > 0; m >>= 1) v += __shfl_xor_sync(0xffffffffu, v, m);
    return v;
}

__global__ void __launch_bounds__(256) k_sg(const float* __restrict__ gu,
                                            const float* __restrict__ temp) {
    int w    = (blockIdx.x * blockDim.x + threadIdx.x) >> 5;  // 0..2047
    int lane = threadIdx.x & 31;
    int b    = w >> 6;
    int rem  = w & 63;                 // side*32 + o
    int side = rem >> 5, o = rem & 31;
    int base = b * C_ + side * 2048 + o;

    float a0 = g_logits[base + lane * 32];
    float a1 = g_logits[base + (lane + 32) * 32];
    float mx = warp_max(fmaxf(a0, a1));
    float e0 = __expf(a0 - mx), e1 = __expf(a1 - mx);
    float inv = 1.0f / warp_sum(e0 + e1);
    float p0 = e0 * inv, p1 = e1 * inv;
    g_V[base + lane * 32]        = p0;
    g_V[base + (lane + 32) * 32] = p1;

    float tc = fmaxf(fminf(fmaxf(temp[0], EPSF), 2.0f), EPSF);
    float invt = 1.0f / tc;

    float u0 = fmaxf(__ldcs(&gu[base + lane * 32]), EPSF);
    float u1 = fmaxf(__ldcs(&gu[base + (lane + 32) * 32]), EPSF);
    float g0 = -__logf(-__logf(u0) + EPSF);
    float g1 = -__logf(-__logf(u1) + EPSF);
    float l0 = (__logf(p0 + EPSF) + g0) * invt;
    float l1 = (__logf(p1 + EPSF) + g1) * invt;
    mx = warp_max(fmaxf(l0, l1));
    e0 = __expf(l0 - mx); e1 = __expf(l1 - mx);
    inv = 1.0f / warp_sum(e0 + e1);
    float m0 = e0 * inv, m1 = e1 * inv;

    __nv_bfloat16 h0 = __float2bfloat16_rn(m0);
    __nv_bfloat16 h1 = __float2bfloat16_rn(m1);
    __nv_bfloat16 q0 = __float2bfloat16_rn(m0 - __bfloat162float(h0));
    __nv_bfloat16 q1 = __float2bfloat16_rn(m1 - __bfloat162float(h1));
    size_t i0 = (size_t)b * C_ + lane * 64 + side * 32 + o;
    size_t i1 = (size_t)b * C_ + (lane + 32) * 64 + side * 32 + o;
    g_mh[i0] = h0; g_ml[i0] = q0;
    g_mh[i1] = h1; g_ml[i1] = q1;
}

// ---------------------------------------------------------------------------
// Kernel 3 (FUSED): blockIdx.x < 64  -> main tensor-core GEMM tile (128 rows)
//                   blockIdx.x >= 64 -> one of 512 h-partial blocks (W1 GEMM
//                   slice, REDG into g_h), co-scheduled with main blocks.
// (R14 configuration: 55 KB smem -> 4 blocks/SM; occupancy > tile efficiency.)
// ---------------------------------------------------------------------------
#define LDSM4(r, a) \
    asm volatile("ldmatrix.sync.aligned.m8n8.x4.shared.b16 {%0,%1,%2,%3}, [%4];" \
        : "=r"((r)[0]), "=r"((r)[1]), "=r"((r)[2]), "=r"((r)[3]) : "r"(a))
#define LDSM4T(r, a) \
    asm volatile("ldmatrix.sync.aligned.m8n8.x4.trans.shared.b16 {%0,%1,%2,%3}, [%4];" \
        : "=r"((r)[0]), "=r"((r)[1]), "=r"((r)[2]), "=r"((r)[3]) : "r"(a))
#define MMA16816(d, a, b0, b1) \
    asm volatile("mma.sync.aligned.m16n8k16.row.col.f32.bf16.bf16.f32 " \
        "{%0,%1,%2,%3}, {%4,%5,%6,%7}, {%8,%9}, {%0,%1,%2,%3};" \
        : "+f"((d)[0]), "+f"((d)[1]), "+f"((d)[2]), "+f"((d)[3]) \
        : "r"((a)[0]), "r"((a)[1]), "r"((a)[2]), "r"((a)[3]), "r"(b0), "r"(b1))

#define SM_MH 0
#define SM_ML 9216
#define SM_XH 18432
#define SM_XL 36864
#define SM_TOT 55296

extern __shared__ char smc[];

__device__ __forceinline__ void h_part_body(const float* __restrict__ W1, int hb) {
    float* Vs = (float*)smc;                 // B_*68 floats = 8704 B
    int jt = hb & 7;
    int ks = hb >> 3;                        // 0..63, 64 k each

    for (int idx = threadIdx.x; idx < B_ * 64; idx += 256) {
        int b = idx >> 6, k = idx & 63;
        Vs[b * 68 + k] = g_V[b * C_ + ks * 64 + k];
    }
    __syncthreads();

    int j  = jt * 32 + (threadIdx.x & 31);
    int bg = threadIdx.x >> 5;

    float acc[4] = {0.f, 0.f, 0.f, 0.f};
    const float* wp = W1 + (size_t)(ks * 64) * 256 + j;
#pragma unroll
    for (int kb = 0; kb < 8; kb++) {
        float wv[8];
#pragma unroll
        for (int u = 0; u < 8; u++) wv[u] = wp[(size_t)(kb * 8 + u) * 256];
#pragma unroll
        for (int u = 0; u < 8; u++) {
            int k = kb * 8 + u;
#pragma unroll
            for (int q = 0; q < 4; q++)
                acc[q] += Vs[(bg * 4 + q) * 68 + k] * wv[u];
        }
    }
#pragma unroll
    for (int q = 0; q < 4; q++)
        atomicAdd(&g_h[(size_t)(bg * 4 + q) * L_ + j], acc[q]);
}

__global__ void __launch_bounds__(256) k_fused(const float* __restrict__ x,
                                               float* __restrict__ y,
                                               const float* __restrict__ W1) {
    if (blockIdx.x >= 64) {                  // ---- h-partial branch ----
        h_part_body(W1, (blockIdx.x - 64) * 32 + blockIdx.y);
        return;
    }

    // ---- main GEMM branch (R14 128-row configuration) ----
    int tid = threadIdx.x, lane = tid & 31, w = tid >> 5;
    int b = blockIdx.y;
    int pbase = blockIdx.x * 128;

    uint32_t sb = (uint32_t)__cvta_generic_to_shared(smc);

    const uint4* mh4 = (const uint4*)(g_mh + (size_t)b * C_);
    const uint4* ml4 = (const uint4*)(g_ml + (size_t)b * C_);
#pragma unroll
    for (int k = 0; k < 2; k++) {
        int idx = tid + k * 256;
        int row = idx >> 3, ch = idx & 7;
        *(uint4*)(smc + SM_MH + row * 144 + ch * 16) = mh4[idx];
        *(uint4*)(smc + SM_ML + row * 144 + ch * 16) = ml4[idx];
    }

    const float4* xg = (const float4*)(x + ((size_t)b * P_ + pbase) * SI_);
#pragma unroll
    for (int k = 0; k < 8; k++) {
        int idx = tid + k * 256;
        int row = idx >> 4, f4 = idx & 15;
        float4 v = __ldcs(&xg[idx]);                 // streaming read-once
        __nv_bfloat16 h0 = __float2bfloat16_rn(v.x);
        __nv_bfloat16 h1 = __float2bfloat16_rn(v.y);
        __nv_bfloat16 h2 = __float2bfloat16_rn(v.z);
        __nv_bfloat16 h3 = __float2bfloat16_rn(v.w);
        __nv_bfloat16 l0 = __float2bfloat16_rn(v.x - __bfloat162float(h0));
        __nv_bfloat16 l1 = __float2bfloat16_rn(v.y - __bfloat162float(h1));
        __nv_bfloat16 l2 = __float2bfloat16_rn(v.z - __bfloat162float(h2));
        __nv_bfloat16 l3 = __float2bfloat16_rn(v.w - __bfloat162float(h3));
        __nv_bfloat162 hA = {h0, h1}, hB = {h2, h3};
        __nv_bfloat162 lA = {l0, l1}, lB = {l2, l3};
        uint2 hp = make_uint2(*(uint32_t*)&hA, *(uint32_t*)&hB);
        uint2 lp = make_uint2(*(uint32_t*)&lA, *(uint32_t*)&lB);
        *(uint2*)(smc + SM_XH + row * 144 + f4 * 8) = hp;
        *(uint2*)(smc + SM_XL + row * 144 + f4 * 8) = lp;
    }
    __syncthreads();

    float d[8][4];
#pragma unroll
    for (int nt = 0; nt < 8; nt++)
#pragma unroll
        for (int q = 0; q < 4; q++) d[nt][q] = 0.f;

    int lrow = lane & 15;
    uint32_t lcol = (lane >> 4) * 16;

#pragma unroll
    for (int ks = 0; ks < 4; ks++) {
        uint32_t ah[4], al[4];
        uint32_t aoff = (uint32_t)((w * 16 + lrow) * 144 + ks * 32) + lcol;
        LDSM4(ah, sb + SM_XH + aoff);
        LDSM4(al, sb + SM_XL + aoff);

        uint32_t bh[4][4], bl[4][4];
        uint32_t brow = (uint32_t)((ks * 16 + lrow) * 144) + lcol;
#pragma unroll
        for (int np = 0; np < 4; np++) {
            LDSM4T(bh[np], sb + SM_MH + brow + np * 32);
            LDSM4T(bl[np], sb + SM_ML + brow + np * 32);
        }
#pragma unroll
        for (int nt = 0; nt < 8; nt++) {
            uint32_t bh0 = bh[nt >> 1][(nt & 1) * 2], bh1 = bh[nt >> 1][(nt & 1) * 2 + 1];
            uint32_t bl0 = bl[nt >> 1][(nt & 1) * 2], bl1 = bl[nt >> 1][(nt & 1) * 2 + 1];
            MMA16816(d[nt], ah, bh0, bh1);
            MMA16816(d[nt], al, bh0, bh1);
            MMA16816(d[nt], ah, bl0, bl1);
        }
    }

    // epilogue: fragments -> smem [128][72], then coalesced streaming STG.128
    __syncthreads();
    float* eb = (float*)(smc + SM_XH);
    int r0 = w * 16 + (lane >> 2);
    int cb = (lane & 3) * 2;
#pragma unroll
    for (int nt = 0; nt < 8; nt++) {
        int col = nt * 8 + cb;
        *(float2*)(eb + (size_t)r0 * 72 + col)       = make_float2(d[nt][0], d[nt][1]);
        *(float2*)(eb + (size_t)(r0 + 8) * 72 + col) = make_float2(d[nt][2], d[nt][3]);
    }
    __syncwarp();

    float* yb = y + ((size_t)b * P_ + pbase) * 128;
    int ch = lane & 7;
#define CLIP01(v) fminf(fmaxf((v), 0.f), 1.f)
#pragma unroll
    for (int rg = 0; rg < 4; rg++) {
        int row = w * 16 + rg * 4 + (lane >> 3);
        float4 vl = *(float4*)(eb + (size_t)row * 72 + ch * 4);
        float4 vr = *(float4*)(eb + (size_t)row * 72 + 32 + ch * 4);
        float s0 = vl.x + vr.x, s1 = vl.y + vr.y, s2 = vl.z + vr.z, s3 = vl.w + vr.w;
        float e0 = vl.x - vr.x, e1 = vl.y - vr.y, e2 = vl.z - vr.z, e3 = vl.w - vr.w;
        float* orow = yb + (size_t)row * 128 + ch * 4;
        float4 o;
        o.x = CLIP01(s0); o.y = CLIP01(s1); o.z = CLIP01(s2); o.w = CLIP01(s3);
        __stcs((float4*)(orow), o);
        o.x = CLIP01(s0 - 1.f); o.y = CLIP01(s1 - 1.f); o.z = CLIP01(s2 - 1.f); o.w = CLIP01(s3 - 1.f);
        __stcs((float4*)(orow + 32), o);
        o.x = CLIP01(e0); o.y = CLIP01(e1); o.z = CLIP01(e2); o.w = CLIP01(e3);
        __stcs((float4*)(orow + 64), o);
        o.x = CLIP01(-e0); o.y = CLIP01(-e1); o.z = CLIP01(-e2); o.w = CLIP01(-e3);
        __stcs((float4*)(orow + 96), o);
    }
#undef CLIP01
}

// ---------------------------------------------------------------------------
// Kernel 4: v_encode = leaky(g_h + b1) @ W2 + b2. grid (8 jt, 32 b).
// ---------------------------------------------------------------------------
__global__ void __launch_bounds__(256) k_venc(const float* __restrict__ b1,
                                              const float* __restrict__ W2,
                                              const float* __restrict__ b2,
                                              float* __restrict__ out) {
    int jt = blockIdx.x, b = blockIdx.y;
    int tid = threadIdx.x, lane = tid & 31, w = tid >> 5;
    __shared__ float sh[L_];
    __shared__ float red[8][32];

    float s = g_h[b * L_ + tid] + b1[tid];
    sh[tid] = (s >= 0.f) ? s : 0.01f * s;
    __syncthreads();

    int j = jt * 32 + lane;
    float a = 0.f;
    const float* wp = W2 + (size_t)(w * 32) * L_ + j;
#pragma unroll
    for (int k = 0; k < 32; k++)
        a += sh[w * 32 + k] * wp[(size_t)k * L_];
    red[w][lane] = a;
    __syncthreads();
    if (w == 0) {
        float t = a + b2[j];
#pragma unroll
        for (int q = 1; q < 8; q++) t += red[q][lane];
        out[YSZ + b * L_ + j] = t;
    }
}

// ---------------------------------------------------------------------------
extern "C" void kernel_launch(void* const* d_in, const int* in_sizes, int n_in,
                              void* d_out, int out_size) {
    const float* x    = (const float*)d_in[0];
    const float* lat  = (const float*)d_in[1];
    const float* gu   = (const float*)d_in[2];
    const float* Kl   = (const float*)d_in[3];
    const float* Kr   = (const float*)d_in[4];
    const float* temp = (const float*)d_in[5];
    const float* W1   = (const float*)d_in[6];
    const float* b1   = (const float*)d_in[7];
    const float* W2   = (const float*)d_in[8];
    const float* b2   = (const float*)d_in[9];
    float* out = (float*)d_out;

    cudaFuncSetAttribute(k_fused, cudaFuncAttributeMaxDynamicSharedMemorySize, SM_TOT);

    // 4 serial launches; h_part co-scheduled inside k_fused (x >= 64 blocks).
    k_logits<<<128, 256>>>(lat, Kl, Kr);                 // also zeros g_h
    k_sg<<<256, 256>>>(gu, temp);
    k_fused<<<dim3(80, 32), 256, SM_TOT>>>(x, out, W1);  // 64 main + 16 h_part per y
    k_venc<<<dim3(8, 32), 256>>>(b1, W2, b2, out);
}

// round 17
// speedup vs baseline: 1.2420x; 1.1271x over previous
#include <cuda_runtime.h>
#include <cuda_bf16.h>
#include <cstdint>

#define EPSF 1.1920928955078125e-07f

// Problem constants
#define B_   32
#define P_   8192
#define SI_  64
#define SO_  32
#define L_   256
#define C_   4096          // 2 * SI * SO
#define YSZ  33554432      // B*P*128

// Device scratch (no allocations allowed)
__device__ float g_logits[B_ * C_];
__device__ float g_V[B_ * C_];
__device__ float g_h[B_ * L_];                // atomically-accumulated hidden pre-act
__device__ __nv_bfloat16 g_mh[B_ * C_];       // mask hi (bf16)
__device__ __nv_bfloat16 g_ml[B_ * C_];       // mask lo residual (bf16)

// ---------------------------------------------------------------------------
// Kernel 1: logits[b,c] = sum_l latent[b,l] * K[side(c)][l, i, o].
// Blocks 0..31 additionally zero g_h (consumed by fused kernel's atomics).
// ---------------------------------------------------------------------------
__global__ void __launch_bounds__(256) k_logits(const float* __restrict__ lat,
                                                const float* __restrict__ Kl,
                                                const float* __restrict__ Kr) {
    __shared__ float slat[B_ * L_];  // 32 KB
    if (blockIdx.x < 32) g_h[blockIdx.x * L_ + threadIdx.x] = 0.f;
    for (int k = threadIdx.x; k < B_ * L_; k += 256) slat[k] = lat[k];
    __syncthreads();

    int c  = blockIdx.x * 32 + (threadIdx.x & 31);
    int bg = threadIdx.x >> 5;                // 0..7 -> batches bg*4..bg*4+3
    const float* Ksrc = (c & 2048) ? Kr : Kl;
    int cc = c & 2047;

    float acc[4] = {0.f, 0.f, 0.f, 0.f};
    const float* s0 = slat + (bg * 4) * L_;
#pragma unroll 4
    for (int l = 0; l < L_; l += 8) {
        float kv[8];
#pragma unroll
        for (int u = 0; u < 8; u++) kv[u] = Ksrc[(size_t)(l + u) * 2048 + cc];
#pragma unroll
        for (int u = 0; u < 8; u++) {
#pragma unroll
            for (int q = 0; q < 4; q++)
                acc[q] += s0[q * L_ + l + u] * kv[u];
        }
    }
#pragma unroll
    for (int q = 0; q < 4; q++)
        g_logits[(size_t)(bg * 4 + q) * C_ + c] = acc[q];
}

// ---------------------------------------------------------------------------
// Kernel 2: warp-per-(b,side,o) column softmax + gumbel-softmax, shfl-only.
// ---------------------------------------------------------------------------
__device__ __forceinline__ float warp_max(float v) {
#pragma unroll
    for (int m = 16; m > 0; m >>= 1) v = fmaxf(v, __shfl_xor_sync(0xffffffffu, v, m));
    return v;
}
__device__ __forceinline__ float warp_sum(float v) {
#pragma unroll
    for (int m = 16; m > 0; m >>= 1) v += __shfl_xor_sync(0xffffffffu, v, m);
    return v;
}

__global__ void __launch_bounds__(256) k_sg(const float* __restrict__ gu,
                                            const float* __restrict__ temp) {
    int w    = (blockIdx.x * blockDim.x + threadIdx.x) >> 5;  // 0..2047
    int lane = threadIdx.x & 31;
    int b    = w >> 6;
    int rem  = w & 63;                 // side*32 + o
    int side = rem >> 5, o = rem & 31;
    int base = b * C_ + side * 2048 + o;

    float a0 = g_logits[base + lane * 32];
    float a1 = g_logits[base + (lane + 32) * 32];
    float mx = warp_max(fmaxf(a0, a1));
    float e0 = __expf(a0 - mx), e1 = __expf(a1 - mx);
    float inv = 1.0f / warp_sum(e0 + e1);
    float p0 = e0 * inv, p1 = e1 * inv;
    g_V[base + lane * 32]        = p0;
    g_V[base + (lane + 32) * 32] = p1;

    float tc = fmaxf(fminf(fmaxf(temp[0], EPSF), 2.0f), EPSF);
    float invt = 1.0f / tc;

    float u0 = fmaxf(gu[base + lane * 32], EPSF);
    float u1 = fmaxf(gu[base + (lane + 32) * 32], EPSF);
    float g0 = -__logf(-__logf(u0) + EPSF);
    float g1 = -__logf(-__logf(u1) + EPSF);
    float l0 = (__logf(p0 + EPSF) + g0) * invt;
    float l1 = (__logf(p1 + EPSF) + g1) * invt;
    mx = warp_max(fmaxf(l0, l1));
    e0 = __expf(l0 - mx); e1 = __expf(l1 - mx);
    inv = 1.0f / warp_sum(e0 + e1);
    float m0 = e0 * inv, m1 = e1 * inv;

    __nv_bfloat16 h0 = __float2bfloat16_rn(m0);
    __nv_bfloat16 h1 = __float2bfloat16_rn(m1);
    __nv_bfloat16 q0 = __float2bfloat16_rn(m0 - __bfloat162float(h0));
    __nv_bfloat16 q1 = __float2bfloat16_rn(m1 - __bfloat162float(h1));
    size_t i0 = (size_t)b * C_ + lane * 64 + side * 32 + o;
    size_t i1 = (size_t)b * C_ + (lane + 32) * 64 + side * 32 + o;
    g_mh[i0] = h0; g_ml[i0] = q0;
    g_mh[i1] = h1; g_ml[i1] = q1;
}

// ---------------------------------------------------------------------------
// Kernel 3 (FUSED): blockIdx.x < 64  -> main tensor-core GEMM tile (128 rows)
//                   blockIdx.x >= 64 -> one of 512 h-partial blocks (W1 GEMM
//                   slice, REDG into g_h), co-scheduled with main blocks so
//                   its DRAM/FMA work hides under the main GEMM.
// ---------------------------------------------------------------------------
#define LDSM4(r, a) \
    asm volatile("ldmatrix.sync.aligned.m8n8.x4.shared.b16 {%0,%1,%2,%3}, [%4];" \
        : "=r"((r)[0]), "=r"((r)[1]), "=r"((r)[2]), "=r"((r)[3]) : "r"(a))
#define LDSM4T(r, a) \
    asm volatile("ldmatrix.sync.aligned.m8n8.x4.trans.shared.b16 {%0,%1,%2,%3}, [%4];" \
        : "=r"((r)[0]), "=r"((r)[1]), "=r"((r)[2]), "=r"((r)[3]) : "r"(a))
#define MMA16816(d, a, b0, b1) \
    asm volatile("mma.sync.aligned.m16n8k16.row.col.f32.bf16.bf16.f32 " \
        "{%0,%1,%2,%3}, {%4,%5,%6,%7}, {%8,%9}, {%0,%1,%2,%3};" \
        : "+f"((d)[0]), "+f"((d)[1]), "+f"((d)[2]), "+f"((d)[3]) \
        : "r"((a)[0]), "r"((a)[1]), "r"((a)[2]), "r"((a)[3]), "r"(b0), "r"(b1))

#define SM_MH 0
#define SM_ML 9216
#define SM_XH 18432
#define SM_XL 36864
#define SM_TOT 55296

extern __shared__ char smc[];

__device__ __forceinline__ void h_part_body(const float* __restrict__ W1, int hb) {
    float* Vs = (float*)smc;                 // B_*68 floats = 8704 B
    int jt = hb & 7;
    int ks = hb >> 3;                        // 0..63, 64 k each

    for (int idx = threadIdx.x; idx < B_ * 64; idx += 256) {
        int b = idx >> 6, k = idx & 63;
        Vs[b * 68 + k] = g_V[b * C_ + ks * 64 + k];
    }
    __syncthreads();

    int j  = jt * 32 + (threadIdx.x & 31);
    int bg = threadIdx.x >> 5;

    float acc[4] = {0.f, 0.f, 0.f, 0.f};
    const float* wp = W1 + (size_t)(ks * 64) * 256 + j;
#pragma unroll
    for (int kb = 0; kb < 8; kb++) {
        float wv[8];
#pragma unroll
        for (int u = 0; u < 8; u++) wv[u] = wp[(size_t)(kb * 8 + u) * 256];
#pragma unroll
        for (int u = 0; u < 8; u++) {
            int k = kb * 8 + u;
#pragma unroll
            for (int q = 0; q < 4; q++)
                acc[q] += Vs[(bg * 4 + q) * 68 + k] * wv[u];
        }
    }
#pragma unroll
    for (int q = 0; q < 4; q++)
        atomicAdd(&g_h[(size_t)(bg * 4 + q) * L_ + j], acc[q]);
}

__global__ void __launch_bounds__(256) k_fused(const float* __restrict__ x,
                                               float* __restrict__ y,
                                               const float* __restrict__ W1) {
    if (blockIdx.x >= 64) {                  // ---- h-partial branch ----
        h_part_body(W1, (blockIdx.x - 64) * 32 + blockIdx.y);
        return;
    }

    // ---- main GEMM branch ----
    int tid = threadIdx.x, lane = tid & 31, w = tid >> 5;
    int b = blockIdx.y;
    int pbase = blockIdx.x * 128;

    uint32_t sb = (uint32_t)__cvta_generic_to_shared(smc);

    const uint4* mh4 = (const uint4*)(g_mh + (size_t)b * C_);
    const uint4* ml4 = (const uint4*)(g_ml + (size_t)b * C_);
#pragma unroll
    for (int k = 0; k < 2; k++) {
        int idx = tid + k * 256;
        int row = idx >> 3, ch = idx & 7;
        *(uint4*)(smc + SM_MH + row * 144 + ch * 16) = mh4[idx];
        *(uint4*)(smc + SM_ML + row * 144 + ch * 16) = ml4[idx];
    }

    const float4* xg = (const float4*)(x + ((size_t)b * P_ + pbase) * SI_);
#pragma unroll
    for (int k = 0; k < 8; k++) {
        int idx = tid + k * 256;
        int row = idx >> 4, f4 = idx & 15;
        float4 v = __ldcs(&xg[idx]);                 // streaming read-once
        __nv_bfloat16 h0 = __float2bfloat16_rn(v.x);
        __nv_bfloat16 h1 = __float2bfloat16_rn(v.y);
        __nv_bfloat16 h2 = __float2bfloat16_rn(v.z);
        __nv_bfloat16 h3 = __float2bfloat16_rn(v.w);
        __nv_bfloat16 l0 = __float2bfloat16_rn(v.x - __bfloat162float(h0));
        __nv_bfloat16 l1 = __float2bfloat16_rn(v.y - __bfloat162float(h1));
        __nv_bfloat16 l2 = __float2bfloat16_rn(v.z - __bfloat162float(h2));
        __nv_bfloat16 l3 = __float2bfloat16_rn(v.w - __bfloat162float(h3));
        __nv_bfloat162 hA = {h0, h1}, hB = {h2, h3};
        __nv_bfloat162 lA = {l0, l1}, lB = {l2, l3};
        uint2 hp = make_uint2(*(uint32_t*)&hA, *(uint32_t*)&hB);
        uint2 lp = make_uint2(*(uint32_t*)&lA, *(uint32_t*)&lB);
        *(uint2*)(smc + SM_XH + row * 144 + f4 * 8) = hp;
        *(uint2*)(smc + SM_XL + row * 144 + f4 * 8) = lp;
    }
    __syncthreads();

    float d[8][4];
#pragma unroll
    for (int nt = 0; nt < 8; nt++)
#pragma unroll
        for (int q = 0; q < 4; q++) d[nt][q] = 0.f;

    int lrow = lane & 15;
    uint32_t lcol = (lane >> 4) * 16;

#pragma unroll
    for (int ks = 0; ks < 4; ks++) {
        uint32_t ah[4], al[4];
        uint32_t aoff = (uint32_t)((w * 16 + lrow) * 144 + ks * 32) + lcol;
        LDSM4(ah, sb + SM_XH + aoff);
        LDSM4(al, sb + SM_XL + aoff);

        uint32_t bh[4][4], bl[4][4];
        uint32_t brow = (uint32_t)((ks * 16 + lrow) * 144) + lcol;
#pragma unroll
        for (int np = 0; np < 4; np++) {
            LDSM4T(bh[np], sb + SM_MH + brow + np * 32);
            LDSM4T(bl[np], sb + SM_ML + brow + np * 32);
        }
#pragma unroll
        for (int nt = 0; nt < 8; nt++) {
            uint32_t bh0 = bh[nt >> 1][(nt & 1) * 2], bh1 = bh[nt >> 1][(nt & 1) * 2 + 1];
            uint32_t bl0 = bl[nt >> 1][(nt & 1) * 2], bl1 = bl[nt >> 1][(nt & 1) * 2 + 1];
            MMA16816(d[nt], ah, bh0, bh1);
            MMA16816(d[nt], al, bh0, bh1);
            MMA16816(d[nt], ah, bl0, bl1);
        }
    }

    // epilogue: fragments -> smem [128][72], then coalesced streaming STG.128
    __syncthreads();
    float* eb = (float*)(smc + SM_XH);
    int r0 = w * 16 + (lane >> 2);
    int cb = (lane & 3) * 2;
#pragma unroll
    for (int nt = 0; nt < 8; nt++) {
        int col = nt * 8 + cb;
        *(float2*)(eb + (size_t)r0 * 72 + col)       = make_float2(d[nt][0], d[nt][1]);
        *(float2*)(eb + (size_t)(r0 + 8) * 72 + col) = make_float2(d[nt][2], d[nt][3]);
    }
    __syncwarp();

    float* yb = y + ((size_t)b * P_ + pbase) * 128;
    int ch = lane & 7;
#define CLIP01(v) fminf(fmaxf((v), 0.f), 1.f)
#pragma unroll
    for (int rg = 0; rg < 4; rg++) {
        int row = w * 16 + rg * 4 + (lane >> 3);
        float4 vl = *(float4*)(eb + (size_t)row * 72 + ch * 4);
        float4 vr = *(float4*)(eb + (size_t)row * 72 + 32 + ch * 4);
        float s0 = vl.x + vr.x, s1 = vl.y + vr.y, s2 = vl.z + vr.z, s3 = vl.w + vr.w;
        float e0 = vl.x - vr.x, e1 = vl.y - vr.y, e2 = vl.z - vr.z, e3 = vl.w - vr.w;
        float* orow = yb + (size_t)row * 128 + ch * 4;
        float4 o;
        o.x = CLIP01(s0); o.y = CLIP01(s1); o.z = CLIP01(s2); o.w = CLIP01(s3);
        __stcs((float4*)(orow), o);
        o.x = CLIP01(s0 - 1.f); o.y = CLIP01(s1 - 1.f); o.z = CLIP01(s2 - 1.f); o.w = CLIP01(s3 - 1.f);
        __stcs((float4*)(orow + 32), o);
        o.x = CLIP01(e0); o.y = CLIP01(e1); o.z = CLIP01(e2); o.w = CLIP01(e3);
        __stcs((float4*)(orow + 64), o);
        o.x = CLIP01(-e0); o.y = CLIP01(-e1); o.z = CLIP01(-e2); o.w = CLIP01(-e3);
        __stcs((float4*)(orow + 96), o);
    }
#undef CLIP01
}

// ---------------------------------------------------------------------------
// Kernel 4: v_encode = leaky(g_h + b1) @ W2 + b2. grid (8 jt, 32 b).
// ---------------------------------------------------------------------------
__global__ void __launch_bounds__(256) k_venc(const float* __restrict__ b1,
                                              const float* __restrict__ W2,
                                              const float* __restrict__ b2,
                                              float* __restrict__ out) {
    int jt = blockIdx.x, b = blockIdx.y;
    int tid = threadIdx.x, lane = tid & 31, w = tid >> 5;
    __shared__ float sh[L_];
    __shared__ float red[8][32];

    float s = g_h[b * L_ + tid] + b1[tid];
    sh[tid] = (s >= 0.f) ? s : 0.01f * s;
    __syncthreads();

    int j = jt * 32 + lane;
    float a = 0.f;
    const float* wp = W2 + (size_t)(w * 32) * L_ + j;
#pragma unroll
    for (int k = 0; k < 32; k++)
        a += sh[w * 32 + k] * wp[(size_t)k * L_];
    red[w][lane] = a;
    __syncthreads();
    if (w == 0) {
        float t = a + b2[j];
#pragma unroll
        for (int q = 1; q < 8; q++) t += red[q][lane];
        out[YSZ + b * L_ + j] = t;
    }
}

// ---------------------------------------------------------------------------
extern "C" void kernel_launch(void* const* d_in, const int* in_sizes, int n_in,
                              void* d_out, int out_size) {
    const float* x    = (const float*)d_in[0];
    const float* lat  = (const float*)d_in[1];
    const float* gu   = (const float*)d_in[2];
    const float* Kl   = (const float*)d_in[3];
    const float* Kr   = (const float*)d_in[4];
    const float* temp = (const float*)d_in[5];
    const float* W1   = (const float*)d_in[6];
    const float* b1   = (const float*)d_in[7];
    const float* W2   = (const float*)d_in[8];
    const float* b2   = (const float*)d_in[9];
    float* out = (float*)d_out;

    cudaFuncSetAttribute(k_fused, cudaFuncAttributeMaxDynamicSharedMemorySize, SM_TOT);

    // 4 serial launches; h_part co-scheduled inside k_fused (x >= 64 blocks).
    k_logits<<<128, 256>>>(lat, Kl, Kr);                 // also zeros g_h
    k_sg<<<256, 256>>>(gu, temp);
    k_fused<<<dim3(80, 32), 256, SM_TOT>>>(x, out, W1);  // 64 main + 16 h_part per y
    k_venc<<<dim3(8, 32), 256>>>(b1, W2, b2, out);
}